// round 13
// baseline (speedup 1.0000x reference)
#include <cuda_runtime.h>

#define D     1024
#define HD    4096
#define LNUM  12
#define VOCAB 50257
#define NT    512
#define NW    16
#define RSLOT 3
#define CHUNK_F 1024   // floats per chunk (4KB)

// ---------------- global scratch ----------------
__device__ float g_x[D];
__device__ float g_k[D];
__device__ float g_v[D];
__device__ float g_r[D];
__device__ float g_k2[HD];
__device__ float g_r2[D];

// ---------------- barrier state ----------------
__device__ unsigned g_bar_gen = 0;
__device__ unsigned g_leaf[8 * 128];
__device__ unsigned g_root = 0;

__device__ __forceinline__ void grid_barrier(int nb) {
    __syncthreads();
    if (threadIdx.x == 0) {
        __threadfence();
        unsigned gen = *((volatile unsigned*)&g_bar_gen);
        int leaf = blockIdx.x & 7;
        unsigned target = (unsigned)((nb >> 3) + ((blockIdx.x & 7) < (nb & 7) ? 1 : 0));
        if (atomicAdd(&g_leaf[leaf * 128], 1u) == target - 1u) {
            g_leaf[leaf * 128] = 0;
            __threadfence();
            if (atomicAdd(&g_root, 1u) == 7u) {
                g_root = 0;
                __threadfence();
                atomicAdd(&g_bar_gen, 1u);
            }
        }
        while (*((volatile unsigned*)&g_bar_gen) == gen) { }
        __threadfence();
    }
    __syncthreads();
}

// ---------------- block-wide sum ----------------
__device__ __forceinline__ float block_sum(float v, float* sred) {
    int lane = threadIdx.x & 31, wid = threadIdx.x >> 5;
    #pragma unroll
    for (int o = 16; o; o >>= 1) v += __shfl_xor_sync(0xffffffffu, v, o);
    if (lane == 0) sred[wid] = v;
    __syncthreads();
    float t = 0.f;
    if (wid == 0) {
        t = (lane < NW) ? sred[lane] : 0.f;
        #pragma unroll
        for (int o = 8; o; o >>= 1) t += __shfl_xor_sync(0xffffffffu, t, o);
        if (lane == 0) sred[0] = t;
    }
    __syncthreads();
    float r = sred[0];
    __syncthreads();
    return r;
}

// ---------------- mbarrier / bulk helpers (verbatim from passing R6) ----------------
__device__ __forceinline__ unsigned s2u(const void* p) {
    return (unsigned)__cvta_generic_to_shared(p);
}
__device__ __forceinline__ void mb_init(unsigned a) {
    asm volatile("mbarrier.init.shared.b64 [%0], 1;" :: "r"(a) : "memory");
}
__device__ __forceinline__ void mb_expect(unsigned a, unsigned bytes) {
    asm volatile("mbarrier.arrive.expect_tx.shared.b64 _, [%0], %1;"
                 :: "r"(a), "r"(bytes) : "memory");
}
__device__ __forceinline__ void mb_wait(unsigned a, unsigned parity) {
    unsigned done = 0;
    while (!done) {
        asm volatile("{\n\t.reg .pred p;\n\t"
                     "mbarrier.try_wait.parity.acquire.cta.shared::cta.b64 p, [%1], %2, 0x989680;\n\t"
                     "selp.b32 %0,1,0,p;\n\t}"
                     : "=r"(done) : "r"(a), "r"(parity) : "memory");
    }
}
__device__ __forceinline__ void bulk_cp(unsigned sdst, const void* g, unsigned bytes, unsigned mb) {
    asm volatile("cp.async.bulk.shared::cta.global.mbarrier::complete_tx::bytes "
                 "[%0], [%1], %2, [%3];"
                 :: "r"(sdst), "l"(g), "r"(bytes), "r"(mb) : "memory");
}

__global__ __launch_bounds__(NT, 1) void rwkv_persistent(
    const int*   __restrict__ ctx,
    const float* __restrict__ st_in,
    const float* __restrict__ emb,
    const float* __restrict__ ln0,
    const float* __restrict__ ln1,
    const float* __restrict__ ln2,
    const float* __restrict__ lnout,
    const float* __restrict__ tmk,
    const float* __restrict__ tmv,
    const float* __restrict__ tmr,
    const float* __restrict__ tfirst,
    const float* __restrict__ tdecay,
    const float* __restrict__ kw,
    const float* __restrict__ vw,
    const float* __restrict__ rw,
    const float* __restrict__ ow,
    const float* __restrict__ ftmk,
    const float* __restrict__ ftmr,
    const float* __restrict__ fkw,
    const float* __restrict__ fvw,
    const float* __restrict__ frw,
    const float* __restrict__ head,
    float* __restrict__ out,
    int nb)
{
    extern __shared__ float smem[];
    // layout: [0 .. NW*RSLOT*CHUNK_F) per-warp rings; then vecS[4096]; 
    float* vecS = smem + NW * RSLOT * CHUNK_F;
    __shared__ float sred[NW];
    __shared__ unsigned long long wbars[NW][RSLOT];

    const int tid  = threadIdx.x;
    const int lane = tid & 31;
    const int w    = tid >> 5;
    const int bid  = blockIdx.x;
    const int gw   = bid * NW + w;
    const int nwG  = nb * NW;
    float* myring  = smem + w * RSLOT * CHUNK_F;

    if (tid < NW * RSLOT) mb_init(s2u(&wbars[tid / RSLOT][tid % RSLOT]));
    __syncthreads();

    float* out_logits = out;
    float* out_state  = out + VOCAB;

    // per-warp pipeline state (uniform within warp)
    long qi = 0, qc = 0, qBase = 0, qEnd = 0;

    auto n1 = [&](int R) { return (long)(gw < R ? (R - 1 - gw) / nwG + 1 : 0); };

    auto issue = [&](const float* g) {
        int slot = (int)(qi % RSLOT);
        if (lane == 0) {
            unsigned mb = s2u(&wbars[w][slot]);
            mb_expect(mb, 4096);
            bulk_cp(s2u(myring + slot * CHUNK_F), g, 4096, mb);
        }
        qi++;
    };
    // top up ring with current-stage chunks (gpf: local idx -> global ptr)
    auto top = [&](auto gpf) {
        while (qi < qEnd && qi - qc < RSLOT) issue(gpf((int)(qi - qBase)));
    };
    // drain current stage: CL chunks per logical row
    auto drain = [&](int CL, auto gpf, auto vpf, auto fin) {
        float s0 = 0.f, s1 = 0.f, s2 = 0.f, s3 = 0.f;
        while (qc < qEnd) {
            top(gpf);
            int slot = (int)(qc % RSLOT);
            mb_wait(s2u(&wbars[w][slot]), (unsigned)((qc / RSLOT) & 1));
            int i = (int)(qc - qBase);
            const float4* a4 = (const float4*)(myring + slot * CHUNK_F);
            const float4* v4 = vpf(i);
            #pragma unroll
            for (int u = 0; u < 8; u++) {
                float4 a = a4[u * 32 + lane];
                float4 b = v4[u * 32 + lane];
                s0 = fmaf(a.x, b.x, s0); s1 = fmaf(a.y, b.y, s1);
                s2 = fmaf(a.z, b.z, s2); s3 = fmaf(a.w, b.w, s3);
            }
            qc++;
            if ((i % CL) == CL - 1) {
                float r = (s0 + s1) + (s2 + s3);
                #pragma unroll
                for (int o = 16; o; o >>= 1) r += __shfl_xor_sync(0xffffffffu, r, o);
                fin(i / CL, r);
                s0 = s1 = s2 = s3 = 0.f;
            }
        }
        qBase = qEnd;
    };

    // mutable stage pointers (set before the corresponding top())
    const float *kwl = kw, *vwl = vw, *rwl = rw;
    const float *owl = ow, *fkwl = fkw, *frwl = frw, *fvwl = fvw;

    auto gpfA = [&](int i) {
        int t = gw + i * nwG;
        int m = t >> 10, r = t & 1023;
        const float* base = (m == 0) ? kwl : ((m == 1) ? vwl : rwl);
        return base + (size_t)r * D;
    };
    auto gpfB = [&](int i) { return owl + (size_t)(gw + i * nwG) * D; };
    auto gpfC = [&](int i) {
        int t = gw + i * nwG;
        return (t < HD) ? fkwl + (size_t)t * D : frwl + (size_t)(t - HD) * D;
    };
    auto gpfD = [&](int i) {
        int row = gw + (i >> 2) * nwG;
        return fvwl + (size_t)row * HD + (size_t)(i & 3) * CHUNK_F;
    };
    auto gpfH = [&](int i) { return head + (size_t)(gw + i * nwG) * D; };

    const float4* vecS4 = (const float4*)vecS;

    // ---------- prologue: pre-issue layer-0 stage A; embedding (block 0) ----------
    qEnd += n1(3 * D);
    top(gpfA);
    if (bid == 0) {
        const float* e = emb + (size_t)ctx[0] * D;
        float ss = 0.f;
        for (int j = tid; j < D; j += NT) { float t = e[j]; ss += t * t; }
        ss = block_sum(ss, sred);
        float inv = rsqrtf(ss * (1.f / D) + 1e-5f);
        for (int j = tid; j < D; j += NT) g_x[j] = e[j] * inv * ln0[j];
    }
    grid_barrier(nb);

    for (int l = 0; l < LNUM; l++) {
        const float* st_l  = st_in     + (size_t)l * 5 * D;
        float*       ost_l = out_state + (size_t)l * 5 * D;

        // ---------- stage A: rms + token-mix prep; k/v/r ----------
        {
            float ss = 0.f;
            for (int j = tid; j < D; j += NT) { float t = g_x[j]; ss += t * t; }
            ss = block_sum(ss, sred);
            float inv = rsqrtf(ss * (1.f / D) + 1e-5f);
            const float* l1 = ln1 + l * D;
            const float* mk = tmk + l * D;
            const float* mv = tmv + l * D;
            const float* mr = tmr + l * D;
            for (int j = tid; j < D; j += NT) {
                float xxj = g_x[j] * inv * l1[j];
                float sa  = st_l[D + j];
                float a_ = mk[j]; vecS[j]         = xxj * a_ + sa * (1.f - a_);
                float b_ = mv[j]; vecS[D + j]     = xxj * b_ + sa * (1.f - b_);
                float c_ = mr[j]; vecS[2 * D + j] = xxj * c_ + sa * (1.f - c_);
                if (bid == 0) ost_l[D + j] = xxj;   // new sa_x
            }
            __syncthreads();
            drain(1, gpfA,
                [&](int i) { return vecS4 + ((gw + i * nwG) >> 10) * 256; },
                [&](int i, float r) {
                    if (lane == 0) {
                        int t = gw + i * nwG;
                        int m = t >> 10, rr = t & 1023;
                        if (m == 0)      g_k[rr] = r;
                        else if (m == 1) g_v[rr] = r;
                        else             g_r[rr] = r;
                    }
                });
        }
        owl = ow + (size_t)l * D * D;
        qEnd += n1(D);
        top(gpfB);
        grid_barrier(nb);

        // ---------- stage B: WKV prep; ow ----------
        {
            const float* tfl = tfirst + l * D;
            const float* tdl = tdecay + l * D;
            for (int j = tid; j < D; j += NT) {
                float k  = g_k[j], v = g_v[j], rr = g_r[j];
                float aa = st_l[2 * D + j], bb = st_l[3 * D + j], pp = st_l[4 * D + j];
                float ww = tfl[j] + k;
                float p  = fmaxf(pp, ww);
                float e1 = __expf(pp - p), e2 = __expf(ww - p);
                float a  = e1 * aa + e2 * v;
                float b  = e1 * bb + e2;
                float sr = 1.f / (1.f + __expf(-rr));
                vecS[j] = sr * (a / b);
                if (bid == 0) {
                    float ww2 = pp + tdl[j];
                    float p2  = fmaxf(ww2, k);
                    float e1b = __expf(ww2 - p2), e2b = __expf(k - p2);
                    ost_l[2 * D + j] = e1b * aa + e2b * v;   // naa
                    ost_l[3 * D + j] = e1b * bb + e2b;       // nbb
                    ost_l[4 * D + j] = p2;                   // pp
                }
            }
            __syncthreads();
            drain(1, gpfB,
                [&](int i) { (void)i; return vecS4; },
                [&](int i, float r) {
                    if (lane == 0) g_x[gw + i * nwG] += r;
                });
        }
        fkwl = fkw + (size_t)l * HD * D;
        frwl = frw + (size_t)l * D * D;
        qEnd += n1(HD + D);
        top(gpfC);
        grid_barrier(nb);

        // ---------- stage C: rms2 + channel-mix prep; fkw/frw ----------
        {
            float ss = 0.f;
            for (int j = tid; j < D; j += NT) { float t = g_x[j]; ss += t * t; }
            ss = block_sum(ss, sred);
            float inv = rsqrtf(ss * (1.f / D) + 1e-5f);
            const float* l2l = ln2  + l * D;
            const float* fmk = ftmk + l * D;
            const float* fmr = ftmr + l * D;
            for (int j = tid; j < D; j += NT) {
                float yyj = g_x[j] * inv * l2l[j];
                float ff  = st_l[j];
                float a_ = fmk[j]; vecS[j]     = yyj * a_ + ff * (1.f - a_);
                float b_ = fmr[j]; vecS[D + j] = yyj * b_ + ff * (1.f - b_);
                if (bid == 0) ost_l[j] = yyj;   // new ff_x
            }
            __syncthreads();
            drain(1, gpfC,
                [&](int i) { return ((gw + i * nwG) < HD) ? vecS4 : (vecS4 + 256); },
                [&](int i, float r) {
                    if (lane == 0) {
                        int t = gw + i * nwG;
                        if (t < HD) { r = fmaxf(r, 0.f); g_k2[t] = r * r; }
                        else        g_r2[t - HD] = r;
                    }
                });
        }
        fvwl = fvw + (size_t)l * D * HD;
        qEnd += n1(D) * 4;
        top(gpfD);
        grid_barrier(nb);

        // ---------- stage D: fvw (4 chunks per row, accumulated in-warp) ----------
        {
            for (int j = tid; j < HD; j += NT) vecS[j] = g_k2[j];
            __syncthreads();
            const float sc = ((l + 1) % 6 == 0) ? 0.5f : 1.0f;
            drain(4, gpfD,
                [&](int i) { return vecS4 + (i & 3) * 256; },
                [&](int ir, float r) {
                    if (lane == 0) {
                        int row = gw + ir * nwG;
                        float sr = 1.f / (1.f + __expf(-g_r2[row]));
                        g_x[row] = (g_x[row] + sr * r) * sc;
                    }
                });
        }
        if (l < LNUM - 1) {
            kwl = kw + (size_t)(l + 1) * D * D;
            vwl = vw + (size_t)(l + 1) * D * D;
            rwl = rw + (size_t)(l + 1) * D * D;
            qEnd += n1(3 * D);
            top(gpfA);
        } else {
            qEnd += n1(VOCAB);
            top(gpfH);
        }
        grid_barrier(nb);
    }

    // ---------- head ----------
    {
        float ss = 0.f;
        for (int j = tid; j < D; j += NT) { float t = g_x[j]; ss += t * t; }
        ss = block_sum(ss, sred);
        float inv = rsqrtf(ss * (1.f / D) + 1e-5f);
        for (int j = tid; j < D; j += NT) vecS[j] = g_x[j] * inv * lnout[j];
        __syncthreads();
        drain(1, gpfH,
            [&](int i) { (void)i; return vecS4; },
            [&](int i, float r) {
                if (lane == 0) out_logits[gw + i * nwG] = r;
            });
    }
}

extern "C" void kernel_launch(void* const* d_in, const int* in_sizes, int n_in,
                              void* d_out, int out_size) {
    (void)in_sizes; (void)n_in; (void)out_size;
    int nb = 0;
    cudaDeviceGetAttribute(&nb, cudaDevAttrMultiProcessorCount, 0);
    if (nb <= 0) nb = 148;
    if (nb > 1024) nb = 1024;

    const int smem_bytes = (NW * RSLOT * CHUNK_F + HD) * (int)sizeof(float);  // 208 KB
    cudaFuncSetAttribute(rwkv_persistent,
                         cudaFuncAttributeMaxDynamicSharedMemorySize, smem_bytes);

    rwkv_persistent<<<nb, NT, smem_bytes>>>(
        (const int*)  d_in[0],   // ctx
        (const float*)d_in[1],   // state
        (const float*)d_in[2],   // emb
        (const float*)d_in[3],   // ln0_w
        (const float*)d_in[4],   // ln1_w
        (const float*)d_in[5],   // ln2_w
        (const float*)d_in[6],   // lnout_w
        (const float*)d_in[7],   // att_tmk
        (const float*)d_in[8],   // att_tmv
        (const float*)d_in[9],   // att_tmr
        (const float*)d_in[10],  // att_tfirst
        (const float*)d_in[11],  // att_tdecay
        (const float*)d_in[12],  // att_kw
        (const float*)d_in[13],  // att_vw
        (const float*)d_in[14],  // att_rw
        (const float*)d_in[15],  // att_ow
        (const float*)d_in[16],  // ffn_tmk
        (const float*)d_in[17],  // ffn_tmr
        (const float*)d_in[18],  // ffn_kw
        (const float*)d_in[19],  // ffn_vw
        (const float*)d_in[20],  // ffn_rw
        (const float*)d_in[21],  // head
        (float*)d_out, nb);
}